// round 9
// baseline (speedup 1.0000x reference)
#include <cuda_runtime.h>

// Quan2d, round 8: four patches per thread (2x2 patch block = 6x6 pixel
// tile), amortizing loads (12 LDG / 4 patches), addressing, tangent reads
// and stores. Scalar tangent-form gates, fused square+tree reduction.
//
// Math: RY(th) = cos(th/2)*[[1,-t],[t,1]], t = tan(th/2); uniform scalars
// cancel in <Z_w> = 2*S_w/n - 1, S_w = sum_{bit_w=0} u^2, n = sum u^2.
// CNOT ring perm h: {0,13,3,14,6,11,5,8,12,1,15,2,10,7,9,4}.

__host__ __device__ constexpr int permIdx(int s) {
    int b0 = (s >> 3) & 1, b1 = (s >> 2) & 1, b2 = (s >> 1) & 1, b3 = s & 1;
    int h0 = b0 ^ b3, h1 = b0 ^ b1 ^ b3, h2 = b1 ^ b2, h3 = b2 ^ b3;
    return (h0 << 3) | (h1 << 2) | (h2 << 1) | h3;
}

__device__ __forceinline__ float frcp_approx(float v) {
    float r; asm("rcp.approx.f32 %0, %1;" : "=f"(r) : "f"(v)); return r;
}

// Full circuit + reduction on one 16-amplitude patch; returns <Z_0..3>.
__device__ __forceinline__ float4 run_patch(const float* __restrict__ ap,
                                            const float* __restrict__ ct) {
    float a[16];
    #pragma unroll
    for (int s = 0; s < 16; s++) a[s] = ap[s];

    // RY layer 1 (tangent form): gate g acts on bit (8 >> g)
    #pragma unroll
    for (int g = 0; g < 4; g++) {
        const float tg = ct[g];
        const int BIT = 8 >> g;
        #pragma unroll
        for (int lo = 0; lo < 16; lo++) {
            if (lo & BIT) continue;
            const float xx = a[lo], yy = a[lo | BIT];
            a[lo]       = fmaf(-tg, yy, xx);
            a[lo | BIT] = fmaf( tg, xx, yy);
        }
    }
    // CNOT ring permutation (register renaming)
    float t[16];
    #pragma unroll
    for (int s = 0; s < 16; s++) t[s] = a[permIdx(s)];
    // RY layer 2
    #pragma unroll
    for (int g = 0; g < 4; g++) {
        const float tg = ct[4 + g];
        const int BIT = 8 >> g;
        #pragma unroll
        for (int lo = 0; lo < 16; lo++) {
            if (lo & BIT) continue;
            const float xx = t[lo], yy = t[lo | BIT];
            t[lo]       = fmaf(-tg, yy, xx);
            t[lo | BIT] = fmaf( tg, xx, yy);
        }
    }
    // fused squares + tree reduction
    float qe[8], s1[8];
    #pragma unroll
    for (int k = 0; k < 8; k++) {
        qe[k] = t[2 * k] * t[2 * k];
        s1[k] = fmaf(t[2 * k + 1], t[2 * k + 1], qe[k]);
    }
    float s2[4];
    #pragma unroll
    for (int k = 0; k < 4; k++) s2[k] = s1[2 * k] + s1[2 * k + 1];
    const float s3a = s2[0] + s2[1];
    const float s3b = s2[2] + s2[3];
    const float n   = s3a + s3b;

    const float S0 = s3a;                                  // wire0: bit3==0
    const float S1 = s2[0] + s2[2];                        // wire1: bit2==0
    const float S2 = (s1[0] + s1[2]) + (s1[4] + s1[6]);    // wire2: bit1==0
    const float S3 = ((qe[0] + qe[1]) + (qe[2] + qe[3]))   // wire3: bit0==0
                   + ((qe[4] + qe[5]) + (qe[6] + qe[7]));

    const float r2 = 2.0f * frcp_approx(n);
    return make_float4(fmaf(S0, r2, -1.0f), fmaf(S1, r2, -1.0f),
                       fmaf(S2, r2, -1.0f), fmaf(S3, r2, -1.0f));
}

__global__ __launch_bounds__(256, 3)
void quan2d_kernel(const float* __restrict__ x,
                   const float* __restrict__ w8,
                   float* __restrict__ out)
{
    __shared__ float cts[8];
    const int tid = threadIdx.x;
    if (tid < 8) cts[tid] = __tanf(0.5f * w8[tid]);
    __syncthreads();

    float ct[8];
    #pragma unroll
    for (int i = 0; i < 8; i++) ct[i] = cts[i];

    // 64 threads per image; thread covers patch rows 2pr,2pr+1 and cols 2k,2k+1
    const int b  = blockIdx.x * 4 + (tid >> 6);   // image
    const int t6 = tid & 63;
    const int pr = t6 >> 3;                        // 0..7
    const int k  = t6 & 7;                         // 0..7
    const float* img = x + (size_t)b * 1024;

    // --- load 6x6 pixel tile: rows 4pr..4pr+5, cols 4k..4k+5 ---
    // rows 4pr..4pr+3 and cols 4k..4k+3 provably in-bounds;
    // rows +4,+5 need pr<7; cols +4,+5 need k<7.
    const bool pA = (pr < 7);
    const bool pB = (k < 7);
    float tile[36];   // tile[6*i + c]
    #pragma unroll
    for (int i = 0; i < 6; i++) {
        const float* base = img + (4 * pr + i) * 32 + 4 * k;
        const bool rok = (i < 4) || pA;
        float4 F = rok ? __ldg((const float4*)base)
                       : make_float4(0.f, 0.f, 0.f, 0.f);
        float2 G = (rok && pB) ? __ldg((const float2*)(base + 4))
                               : make_float2(0.f, 0.f);
        tile[6 * i + 0] = F.x; tile[6 * i + 1] = F.y;
        tile[6 * i + 2] = F.z; tile[6 * i + 3] = F.w;
        tile[6 * i + 4] = G.x; tile[6 * i + 5] = G.y;
    }

    float4* ob = (float4*)out + (size_t)b * 256;

    // --- 4 patches: (dr, dc) in {0,1}^2; patch origin row 2dr, col 2dc ---
    #pragma unroll
    for (int dr = 0; dr < 2; dr++) {
        float4 o[2];
        #pragma unroll
        for (int dc = 0; dc < 2; dc++) {
            float ap[16];
            #pragma unroll
            for (int i = 0; i < 4; i++)
                #pragma unroll
                for (int c = 0; c < 4; c++)
                    ap[4 * i + c] = tile[6 * (2 * dr + i) + 2 * dc + c];
            o[dc] = run_patch(ap, ct);
        }
        float4* op = ob + (2 * pr + dr) * 16 + 2 * k;
        op[0] = o[0];
        op[1] = o[1];
    }
}

extern "C" void kernel_launch(void* const* d_in, const int* in_sizes, int n_in,
                              void* d_out, int out_size)
{
    const float* x = (const float*)d_in[0];   // [B,1,32,32] fp32
    const float* w = (const float*)d_in[1];   // [1,8] fp32
    const int B = in_sizes[0] / 1024;
    quan2d_kernel<<<B / 4, 256>>>(x, w, (float*)d_out);
}